// round 6
// baseline (speedup 1.0000x reference)
#include <cuda_runtime.h>
#include <cstdint>

#define BN 4096
#define CN 80
#define ERRN 4

// ---------------- scratch ----------------
__device__ __align__(16) unsigned char g_lid8[BN];
__device__ int g_idx[2][BN][ERRN];

// ---------------- threefry2x32 (exact JAX semantics) ----------------
__host__ __device__ __forceinline__ uint32_t tf_rotl(uint32_t v, int r) {
    return (v << r) | (v >> (32 - r));
}

// full version (host key derivation + cold paths)
__host__ __device__ __forceinline__ void threefry2x32(uint32_t k0, uint32_t k1,
                                                      uint32_t c0, uint32_t c1,
                                                      uint32_t& o0, uint32_t& o1) {
    uint32_t ks0 = k0, ks1 = k1, ks2 = k0 ^ k1 ^ 0x1BD11BDAu;
    uint32_t x0 = c0 + ks0;
    uint32_t x1 = c1 + ks1;
#define TF_RND(r) { x0 += x1; x1 = tf_rotl(x1, r); x1 ^= x0; }
    TF_RND(13) TF_RND(15) TF_RND(26) TF_RND(6)
    x0 += ks1; x1 += ks2 + 1u;
    TF_RND(17) TF_RND(29) TF_RND(16) TF_RND(24)
    x0 += ks2; x1 += ks0 + 2u;
    TF_RND(13) TF_RND(15) TF_RND(26) TF_RND(6)
    x0 += ks0; x1 += ks1 + 3u;
    TF_RND(17) TF_RND(29) TF_RND(16) TF_RND(24)
    x0 += ks1; x1 += ks2 + 4u;
    TF_RND(13) TF_RND(15) TF_RND(26) TF_RND(6)
    x0 += ks2; x1 += ks0 + 5u;
#undef TF_RND
    o0 = x0; o1 = x1;
}

// Hot path: x0^x1 of threefry((k0,k1),(0,c1)).
// Every rotl as 64-bit mul-by-2^r (IMAD.WIDE, fma pipe) + one 3-input LOP3
// (alu). rotl(x,r) = lo(w)^hi(w), w = x * 2^r (disjoint bits).
__device__ __forceinline__ uint32_t tf_bits(uint32_t k0, uint32_t k1,
                                            uint32_t ks2, uint32_t c1) {
    uint32_t x0 = k0;
    uint32_t x1 = c1 + k1;
#define RND(r) { x0 += x1; \
    unsigned long long w = (unsigned long long)x1 * ((unsigned long long)1u << (r)); \
    x1 = (uint32_t)w ^ (uint32_t)(w >> 32) ^ x0; }
#define GRP_A RND(13) RND(15) RND(26) RND(6)
#define GRP_B RND(17) RND(29) RND(16) RND(24)
    GRP_A
    x0 += k1;  x1 += ks2 + 1u;
    GRP_B
    x0 += ks2; x1 += k0 + 2u;
    GRP_A
    x0 += k0;  x1 += k1 + 3u;
    GRP_B
    x0 += k1;  x1 += ks2 + 4u;
    GRP_A
    x0 += ks2; x1 += k0 + 5u;
#undef GRP_A
#undef GRP_B
#undef RND
    return x0 ^ x1;
}

// ---------------- top-4 helpers (cold path only) ----------------
__device__ __forceinline__ void ins4(unsigned long long* t, unsigned long long c) {
    if (c > t[0])      { t[3] = t[2]; t[2] = t[1]; t[1] = t[0]; t[0] = c; }
    else if (c > t[1]) { t[3] = t[2]; t[2] = t[1]; t[1] = c; }
    else if (c > t[2]) { t[3] = t[2]; t[2] = c; }
    else if (c > t[3]) { t[3] = c; }
}

__device__ __forceinline__ void warp_merge4(unsigned long long* top) {
    for (int off = 16; off > 0; off >>= 1) {
        unsigned long long o0 = __shfl_xor_sync(0xFFFFFFFFu, top[0], off);
        unsigned long long o1 = __shfl_xor_sync(0xFFFFFFFFu, top[1], off);
        unsigned long long o2 = __shfl_xor_sync(0xFFFFFFFFu, top[2], off);
        unsigned long long o3 = __shfl_xor_sync(0xFFFFFFFFu, top[3], off);
        ins4(top, o0); ins4(top, o1); ins4(top, o2); ins4(top, o3);
    }
}

// ---------------- kernels ----------------
// one warp per row; float4 loads (80 floats = 20 float4). Also zeroes d_out.
__global__ __launch_bounds__(256) void k_labelid(const float* __restrict__ labels,
                                                 float* __restrict__ out,
                                                 int out_size) {
    int warp = (blockIdx.x * blockDim.x + threadIdx.x) >> 5;
    int lane = threadIdx.x & 31;
    if (blockIdx.x == 0 && threadIdx.x < out_size) out[threadIdx.x] = 0.0f;
    if (warp >= BN) return;
    const float4* row = (const float4*)(labels + (size_t)warp * CN);
    unsigned best = 0;
    if (lane < CN / 4) {
        float4 v = row[lane];
        unsigned j = (unsigned)lane * 4u;
        if (v.x > 0.5f) best = j;
        if (v.y > 0.5f) best = j + 1;
        if (v.z > 0.5f) best = j + 2;
        if (v.w > 0.5f) best = j + 3;
    }
    best = __reduce_max_sync(0xFFFFFFFFu, best);
    if (lane == 0) g_lid8[warp] = (unsigned char)best;
}

// grid 4096 (one block per row, both keys), block 256.
// Thread t owns contiguous j in [16t, 16t+16).
// Phase 1: per-thread top-1, cand = ((v<<4)+(31-s))*valid  (valid in {0,1});
//          monotone in (v, lower-s), invalid -> 0 < 16 = min valid cand.
// Phase 2: warp/block top-4 of packed bests ((v+1)<<12)|(4095-j).
// Phase 3: exact rescan of the <=4 owner threads.
__global__ __launch_bounds__(256) void k_select(uint32_t a0, uint32_t a1,
                                                uint32_t b0, uint32_t b1) {
    const int row = blockIdx.x;
    const int tid = threadIdx.x;
    const uint32_t ksA2 = a0 ^ a1 ^ 0x1BD11BDAu;
    const uint32_t ksB2 = b0 ^ b1 ^ 0x1BD11BDAu;

    const uint32_t mylid = (uint32_t)g_lid8[row];
    const uint32_t rep = mylid * 0x01010101u;
    const uint4 l4 = reinterpret_cast<const uint4*>(g_lid8)[tid];
    // per-byte validity: 1 if lid[j] != mylid else 0
    uint32_t vw[4];
    vw[0] = __vcmpne4(l4.x, rep) & 0x01010101u;
    vw[1] = __vcmpne4(l4.y, rep) & 0x01010101u;
    vw[2] = __vcmpne4(l4.z, rep) & 0x01010101u;
    vw[3] = __vcmpne4(l4.w, rep) & 0x01010101u;

    const uint32_t cbase = (uint32_t)row * (uint32_t)BN + (uint32_t)tid * 16u;

    uint32_t bestA = 0u, bestB = 0u;
    #pragma unroll
    for (int s = 0; s < 16; s++) {
        uint32_t bitsA = tf_bits(a0, a1, ksA2, cbase + (uint32_t)s);
        uint32_t bitsB = tf_bits(b0, b1, ksB2, cbase + (uint32_t)s);
        uint32_t v01 = __byte_perm(vw[s >> 2], 0u, 0x4440u | (unsigned)(s & 3));
        uint32_t tA = (bitsA >> 5) & 0xFFFFFFF0u;
        uint32_t tB = (bitsB >> 5) & 0xFFFFFFF0u;
        uint32_t cA = tA * v01 + (uint32_t)(31 - s) * v01;   // 2x IMAD
        uint32_t cB = tB * v01 + (uint32_t)(31 - s) * v01;
        bestA = max(bestA, cA);
        bestB = max(bestB, cB);
    }

    // pack per-thread best as ((v+1)<<12) | (4095 - j); 0 if none valid
    __shared__ unsigned long long sA[256], sB[256];
    {
        int jsA = 15 - (int)(bestA & 15u);
        int jsB = 15 - (int)(bestB & 15u);
        unsigned long long pA = (bestA >= 16u)
            ? (((unsigned long long)(bestA >> 4)) << 12) |
              (unsigned long long)(BN - 1 - (tid * 16 + jsA)) : 0ull;
        unsigned long long pB = (bestB >= 16u)
            ? (((unsigned long long)(bestB >> 4)) << 12) |
              (unsigned long long)(BN - 1 - (tid * 16 + jsB)) : 0ull;
        sA[tid] = pA;
        sB[tid] = pB;
    }
    __syncthreads();

    const int wid = tid >> 5, lane = tid & 31;
    if (wid < 2) {
        const unsigned long long* src = wid ? sB : sA;
        const uint32_t kk0 = wid ? b0 : a0;
        const uint32_t kk1 = wid ? b1 : a1;
        const uint32_t kks2 = wid ? ksB2 : ksA2;

        unsigned long long top[4] = {0ull, 0ull, 0ull, 0ull};
        #pragma unroll
        for (int k = 0; k < 8; k++) ins4(top, src[lane + 32 * k]);
        warp_merge4(top);  // all lanes converge to block top-4 of bests

        // phase 3: lanes 0..3 rescan their owner thread exactly
        unsigned long long mytop[4] = {0ull, 0ull, 0ull, 0ull};
        if (lane < 4 && top[lane] != 0ull) {
            int j0 = BN - 1 - (int)(top[lane] & 0xFFFull);
            int to = j0 >> 4;  // owner thread
            uint4 ol4 = reinterpret_cast<const uint4*>(g_lid8)[to];
            uint32_t olw[4] = {ol4.x, ol4.y, ol4.z, ol4.w};
            uint32_t ob = (uint32_t)row * (uint32_t)BN + (uint32_t)to * 16u;
            #pragma unroll
            for (int s = 0; s < 16; s++) {
                uint32_t bits = tf_bits(kk0, kk1, kks2, ob + (uint32_t)s);
                uint32_t lid_s =
                    __byte_perm(olw[s >> 2], 0u, 0x4440u | (unsigned)(s & 3));
                if (lid_s != mylid) {
                    unsigned long long pv =
                        (((unsigned long long)((bits >> 9) + 1u)) << 12) |
                        (unsigned long long)(BN - 1 - (to * 16 + s));
                    ins4(mytop, pv);
                }
            }
        }
        warp_merge4(mytop);  // lanes >=4 contribute zeros
        if (lane < ERRN)
            g_idx[wid][row][lane] = BN - 1 - (int)(mytop[lane] & 0xFFFull);
    }
}

__device__ __forceinline__ float warp_sum(float s) {
    for (int off = 16; off > 0; off >>= 1)
        s += __shfl_xor_sync(0xFFFFFFFFu, s, off);
    return s;
}

__device__ __forceinline__ float dist4(float4 a, float4 b) {
    float dx = a.x - b.x, dy = a.y - b.y, dz = a.z - b.z, dw = a.w - b.w;
    float s = dx * dx + dy * dy + dz * dz + dw * dw;
    s = warp_sum(s);
    return sqrtf(fmaxf(s, 0.0f));
}

// one warp per (row, dir); block 256 = 8 warps = 4 rows; grid 1024.
__global__ __launch_bounds__(256) void k_loss(const float* __restrict__ img,
                                              const float* __restrict__ txt,
                                              float* __restrict__ out) {
    const int w = threadIdx.x >> 5;
    const int lane = threadIdx.x & 31;
    const int i = blockIdx.x * 4 + (w >> 1);
    const int dir = w & 1;

    const float4* img4 = (const float4*)img;
    const float4* txt4 = (const float4*)txt;

    float4 ai = img4[i * 32 + lane];
    float4 ti = txt4[i * 32 + lane];
    float pos = dist4(ai, ti);

    const float4* nsrc = dir ? img4 : txt4;
    float4 anc = dir ? ti : ai;

    float acc = 0.0f;
    #pragma unroll
    for (int k = 0; k < ERRN; k++) {
        int j = g_idx[dir][i][k];
        float4 bj = nsrc[j * 32 + lane];
        float neg = dist4(anc, bj);
        acc += fmaxf(pos - neg + 1.0f, 0.0f);
    }

    __shared__ float ssum[8];
    if (lane == 0) ssum[w] = acc;
    __syncthreads();
    if (threadIdx.x == 0) {
        float t = 0.0f;
        #pragma unroll
        for (int k = 0; k < 8; k++) t += ssum[k];
        atomicAdd(out, t * (1.0f / (float)(BN * ERRN)));
    }
}

// ---------------- launch ----------------
extern "C" void kernel_launch(void* const* d_in, const int* in_sizes, int n_in,
                              void* d_out, int out_size) {
    const float* img    = (const float*)d_in[0];
    const float* txt    = (const float*)d_in[1];
    const float* labels = (const float*)d_in[2];
    float* out = (float*)d_out;

    // jax.random.key(42) -> (0,42); partitionable foldlike split:
    // key_i = threefry((0,42), (0, i)).
    uint32_t a0, a1, b0, b1;
    threefry2x32(0u, 42u, 0u, 0u, a0, a1);  // ks1 (image->text scores)
    threefry2x32(0u, 42u, 0u, 1u, b0, b1);  // ks2 (text->image scores)

    k_labelid<<<512, 256>>>(labels, out, out_size);
    k_select<<<BN, 256>>>(a0, a1, b0, b1);
    k_loss<<<BN / 4, 256>>>(img, txt, out);
}

// round 7
// speedup vs baseline: 1.1321x; 1.1321x over previous
#include <cuda_runtime.h>
#include <cstdint>

#define BN 4096
#define CN 80
#define ERRN 4

// ---------------- scratch ----------------
__device__ __align__(16) unsigned char g_lid8[BN];
__device__ int g_idx[2][BN][ERRN];

// ---------------- threefry2x32 (exact JAX semantics) ----------------
__host__ __device__ __forceinline__ uint32_t tf_rotl(uint32_t v, int r) {
    return (v << r) | (v >> (32 - r));
}

// full version (host key derivation + cold paths)
__host__ __device__ __forceinline__ void threefry2x32(uint32_t k0, uint32_t k1,
                                                      uint32_t c0, uint32_t c1,
                                                      uint32_t& o0, uint32_t& o1) {
    uint32_t ks0 = k0, ks1 = k1, ks2 = k0 ^ k1 ^ 0x1BD11BDAu;
    uint32_t x0 = c0 + ks0;
    uint32_t x1 = c1 + ks1;
#define TF_RND(r) { x0 += x1; x1 = tf_rotl(x1, r); x1 ^= x0; }
    TF_RND(13) TF_RND(15) TF_RND(26) TF_RND(6)
    x0 += ks1; x1 += ks2 + 1u;
    TF_RND(17) TF_RND(29) TF_RND(16) TF_RND(24)
    x0 += ks2; x1 += ks0 + 2u;
    TF_RND(13) TF_RND(15) TF_RND(26) TF_RND(6)
    x0 += ks0; x1 += ks1 + 3u;
    TF_RND(17) TF_RND(29) TF_RND(16) TF_RND(24)
    x0 += ks1; x1 += ks2 + 4u;
    TF_RND(13) TF_RND(15) TF_RND(26) TF_RND(6)
    x0 += ks2; x1 += ks0 + 5u;
#undef TF_RND
    o0 = x0; o1 = x1;
}

// Hot path: x0^x1 of threefry((k0,k1),(0,c1)).
__device__ __forceinline__ uint32_t tf_bits(uint32_t k0, uint32_t k1,
                                            uint32_t ks2, uint32_t c1) {
    uint32_t x0 = k0;
    uint32_t x1 = c1 + k1;
#define RND(r) { x0 += x1; x1 = __funnelshift_l(x1, x1, (r)) ^ x0; }
#define GRP_A RND(13) RND(15) RND(26) RND(6)
#define GRP_B RND(17) RND(29) RND(16) RND(24)
    GRP_A
    x0 += k1;  x1 += ks2 + 1u;
    GRP_B
    x0 += ks2; x1 += k0 + 2u;
    GRP_A
    x0 += k0;  x1 += k1 + 3u;
    GRP_B
    x0 += k1;  x1 += ks2 + 4u;
    GRP_A
    x0 += ks2; x1 += k0 + 5u;
#undef GRP_A
#undef GRP_B
#undef RND
    return x0 ^ x1;
}

// ---------------- top-4 helpers (cold path only) ----------------
__device__ __forceinline__ void ins4(unsigned long long* t, unsigned long long c) {
    if (c > t[0])      { t[3] = t[2]; t[2] = t[1]; t[1] = t[0]; t[0] = c; }
    else if (c > t[1]) { t[3] = t[2]; t[2] = t[1]; t[1] = c; }
    else if (c > t[2]) { t[3] = t[2]; t[2] = c; }
    else if (c > t[3]) { t[3] = c; }
}

__device__ __forceinline__ void warp_merge4(unsigned long long* top) {
    for (int off = 16; off > 0; off >>= 1) {
        unsigned long long o0 = __shfl_xor_sync(0xFFFFFFFFu, top[0], off);
        unsigned long long o1 = __shfl_xor_sync(0xFFFFFFFFu, top[1], off);
        unsigned long long o2 = __shfl_xor_sync(0xFFFFFFFFu, top[2], off);
        unsigned long long o3 = __shfl_xor_sync(0xFFFFFFFFu, top[3], off);
        ins4(top, o0); ins4(top, o1); ins4(top, o2); ins4(top, o3);
    }
}

// ---------------- kernels ----------------
// one warp per row; float4 loads (80 floats = 20 float4). Also zeroes d_out.
__global__ __launch_bounds__(256) void k_labelid(const float* __restrict__ labels,
                                                 float* __restrict__ out,
                                                 int out_size) {
    int warp = (blockIdx.x * blockDim.x + threadIdx.x) >> 5;
    int lane = threadIdx.x & 31;
    if (blockIdx.x == 0 && threadIdx.x < out_size) out[threadIdx.x] = 0.0f;
    if (warp >= BN) return;
    const float4* row = (const float4*)(labels + (size_t)warp * CN);
    unsigned best = 0;
    if (lane < CN / 4) {
        float4 v = row[lane];
        unsigned j = (unsigned)lane * 4u;
        if (v.x > 0.5f) best = j;
        if (v.y > 0.5f) best = j + 1;
        if (v.z > 0.5f) best = j + 2;
        if (v.w > 0.5f) best = j + 3;
    }
    best = __reduce_max_sync(0xFFFFFFFFu, best);
    if (lane == 0) g_lid8[warp] = (unsigned char)best;
}

// grid 4096 (one block per row, both keys), block 256.
// Thread t owns contiguous j in [16t, 16t+16).
// Phase 1: per-thread top-1, cand = ((v<<4)+(31-s))*valid  (valid in {0,1});
//          monotone in (v, lower-s), invalid -> 0 < 16 = min valid cand.
//          unroll 4 (not 16): keeps live chains at 8, regs low, body in I$.
// Phase 2: warp/block top-4 of packed bests ((v+1)<<12)|(4095-j).
// Phase 3: exact rescan of the <=4 owner threads.
__global__ __launch_bounds__(256) void k_select(uint32_t a0, uint32_t a1,
                                                uint32_t b0, uint32_t b1) {
    const int row = blockIdx.x;
    const int tid = threadIdx.x;
    const uint32_t ksA2 = a0 ^ a1 ^ 0x1BD11BDAu;
    const uint32_t ksB2 = b0 ^ b1 ^ 0x1BD11BDAu;

    const uint32_t mylid = (uint32_t)g_lid8[row];
    const uint32_t rep = mylid * 0x01010101u;
    const uint4 l4 = reinterpret_cast<const uint4*>(g_lid8)[tid];
    // per-byte validity: 1 if lid[j] != mylid else 0
    uint32_t vw[4];
    vw[0] = __vcmpne4(l4.x, rep) & 0x01010101u;
    vw[1] = __vcmpne4(l4.y, rep) & 0x01010101u;
    vw[2] = __vcmpne4(l4.z, rep) & 0x01010101u;
    vw[3] = __vcmpne4(l4.w, rep) & 0x01010101u;

    const uint32_t cbase = (uint32_t)row * (uint32_t)BN + (uint32_t)tid * 16u;

    uint32_t bestA = 0u, bestB = 0u;
    #pragma unroll 4
    for (int s = 0; s < 16; s++) {
        uint32_t bitsA = tf_bits(a0, a1, ksA2, cbase + (uint32_t)s);
        uint32_t bitsB = tf_bits(b0, b1, ksB2, cbase + (uint32_t)s);
        uint32_t v01 = __byte_perm(vw[s >> 2], 0u, 0x4440u | (unsigned)(s & 3));
        uint32_t tA = (bitsA >> 5) & 0xFFFFFFF0u;
        uint32_t tB = (bitsB >> 5) & 0xFFFFFFF0u;
        uint32_t cA = tA * v01 + (uint32_t)(31 - s) * v01;
        uint32_t cB = tB * v01 + (uint32_t)(31 - s) * v01;
        bestA = max(bestA, cA);
        bestB = max(bestB, cB);
    }

    // pack per-thread best as ((v+1)<<12) | (4095 - j); 0 if none valid
    __shared__ unsigned long long sA[256], sB[256];
    {
        int jsA = 15 - (int)(bestA & 15u);
        int jsB = 15 - (int)(bestB & 15u);
        unsigned long long pA = (bestA >= 16u)
            ? (((unsigned long long)(bestA >> 4)) << 12) |
              (unsigned long long)(BN - 1 - (tid * 16 + jsA)) : 0ull;
        unsigned long long pB = (bestB >= 16u)
            ? (((unsigned long long)(bestB >> 4)) << 12) |
              (unsigned long long)(BN - 1 - (tid * 16 + jsB)) : 0ull;
        sA[tid] = pA;
        sB[tid] = pB;
    }
    __syncthreads();

    const int wid = tid >> 5, lane = tid & 31;
    if (wid < 2) {
        const unsigned long long* src = wid ? sB : sA;
        const uint32_t kk0 = wid ? b0 : a0;
        const uint32_t kk1 = wid ? b1 : a1;
        const uint32_t kks2 = wid ? ksB2 : ksA2;

        unsigned long long top[4] = {0ull, 0ull, 0ull, 0ull};
        #pragma unroll
        for (int k = 0; k < 8; k++) ins4(top, src[lane + 32 * k]);
        warp_merge4(top);  // all lanes converge to block top-4 of bests

        // phase 3: lanes 0..3 rescan their owner thread exactly
        unsigned long long mytop[4] = {0ull, 0ull, 0ull, 0ull};
        if (lane < 4 && top[lane] != 0ull) {
            int j0 = BN - 1 - (int)(top[lane] & 0xFFFull);
            int to = j0 >> 4;  // owner thread
            uint4 ol4 = reinterpret_cast<const uint4*>(g_lid8)[to];
            uint32_t olw[4] = {ol4.x, ol4.y, ol4.z, ol4.w};
            uint32_t ob = (uint32_t)row * (uint32_t)BN + (uint32_t)to * 16u;
            #pragma unroll 4
            for (int s = 0; s < 16; s++) {
                uint32_t bits = tf_bits(kk0, kk1, kks2, ob + (uint32_t)s);
                uint32_t lid_s =
                    __byte_perm(olw[s >> 2], 0u, 0x4440u | (unsigned)(s & 3));
                if (lid_s != mylid) {
                    unsigned long long pv =
                        (((unsigned long long)((bits >> 9) + 1u)) << 12) |
                        (unsigned long long)(BN - 1 - (to * 16 + s));
                    ins4(mytop, pv);
                }
            }
        }
        warp_merge4(mytop);  // lanes >=4 contribute zeros
        if (lane < ERRN)
            g_idx[wid][row][lane] = BN - 1 - (int)(mytop[lane] & 0xFFFull);
    }
}

__device__ __forceinline__ float warp_sum(float s) {
    for (int off = 16; off > 0; off >>= 1)
        s += __shfl_xor_sync(0xFFFFFFFFu, s, off);
    return s;
}

__device__ __forceinline__ float dist4(float4 a, float4 b) {
    float dx = a.x - b.x, dy = a.y - b.y, dz = a.z - b.z, dw = a.w - b.w;
    float s = dx * dx + dy * dy + dz * dz + dw * dw;
    s = warp_sum(s);
    return sqrtf(fmaxf(s, 0.0f));
}

// one warp per (row, dir); block 256 = 8 warps = 4 rows; grid 1024.
__global__ __launch_bounds__(256) void k_loss(const float* __restrict__ img,
                                              const float* __restrict__ txt,
                                              float* __restrict__ out) {
    const int w = threadIdx.x >> 5;
    const int lane = threadIdx.x & 31;
    const int i = blockIdx.x * 4 + (w >> 1);
    const int dir = w & 1;

    const float4* img4 = (const float4*)img;
    const float4* txt4 = (const float4*)txt;

    float4 ai = img4[i * 32 + lane];
    float4 ti = txt4[i * 32 + lane];
    float pos = dist4(ai, ti);

    const float4* nsrc = dir ? img4 : txt4;
    float4 anc = dir ? ti : ai;

    float acc = 0.0f;
    #pragma unroll
    for (int k = 0; k < ERRN; k++) {
        int j = g_idx[dir][i][k];
        float4 bj = nsrc[j * 32 + lane];
        float neg = dist4(anc, bj);
        acc += fmaxf(pos - neg + 1.0f, 0.0f);
    }

    __shared__ float ssum[8];
    if (lane == 0) ssum[w] = acc;
    __syncthreads();
    if (threadIdx.x == 0) {
        float t = 0.0f;
        #pragma unroll
        for (int k = 0; k < 8; k++) t += ssum[k];
        atomicAdd(out, t * (1.0f / (float)(BN * ERRN)));
    }
}

// ---------------- launch ----------------
extern "C" void kernel_launch(void* const* d_in, const int* in_sizes, int n_in,
                              void* d_out, int out_size) {
    const float* img    = (const float*)d_in[0];
    const float* txt    = (const float*)d_in[1];
    const float* labels = (const float*)d_in[2];
    float* out = (float*)d_out;

    // jax.random.key(42) -> (0,42); partitionable foldlike split:
    // key_i = threefry((0,42), (0, i)).
    uint32_t a0, a1, b0, b1;
    threefry2x32(0u, 42u, 0u, 0u, a0, a1);  // ks1 (image->text scores)
    threefry2x32(0u, 42u, 0u, 1u, b0, b1);  // ks2 (text->image scores)

    k_labelid<<<512, 256>>>(labels, out, out_size);
    k_select<<<BN, 256>>>(a0, a1, b0, b1);
    k_loss<<<BN / 4, 256>>>(img, txt, out);
}

// round 9
// speedup vs baseline: 1.2947x; 1.1437x over previous
#include <cuda_runtime.h>
#include <cstdint>

#define BN 4096
#define CN 80
#define ERRN 4

// ---------------- scratch (static device arrays; no allocation) ----------------
__device__ __align__(16) unsigned char g_lid8[BN];
__device__ uint32_t g_best32[2][BN][256];   // per-thread phase-1 bests (8 MB)
__device__ int g_idx[2][BN][ERRN];

// ---------------- threefry2x32 (exact JAX semantics) ----------------
__host__ __device__ __forceinline__ uint32_t tf_rotl(uint32_t v, int r) {
    return (v << r) | (v >> (32 - r));
}

// full version (host key derivation)
__host__ __device__ __forceinline__ void threefry2x32(uint32_t k0, uint32_t k1,
                                                      uint32_t c0, uint32_t c1,
                                                      uint32_t& o0, uint32_t& o1) {
    uint32_t ks0 = k0, ks1 = k1, ks2 = k0 ^ k1 ^ 0x1BD11BDAu;
    uint32_t x0 = c0 + ks0;
    uint32_t x1 = c1 + ks1;
#define TF_RND(r) { x0 += x1; x1 = tf_rotl(x1, r); x1 ^= x0; }
    TF_RND(13) TF_RND(15) TF_RND(26) TF_RND(6)
    x0 += ks1; x1 += ks2 + 1u;
    TF_RND(17) TF_RND(29) TF_RND(16) TF_RND(24)
    x0 += ks2; x1 += ks0 + 2u;
    TF_RND(13) TF_RND(15) TF_RND(26) TF_RND(6)
    x0 += ks0; x1 += ks1 + 3u;
    TF_RND(17) TF_RND(29) TF_RND(16) TF_RND(24)
    x0 += ks1; x1 += ks2 + 4u;
    TF_RND(13) TF_RND(15) TF_RND(26) TF_RND(6)
    x0 += ks2; x1 += ks0 + 5u;
#undef TF_RND
    o0 = x0; o1 = x1;
}

// Hot path: x0^x1 of threefry((k0,k1),(0,c1)).
__device__ __forceinline__ uint32_t tf_bits(uint32_t k0, uint32_t k1,
                                            uint32_t ks2, uint32_t c1) {
    uint32_t x0 = k0;
    uint32_t x1 = c1 + k1;
#define RND(r) { x0 += x1; x1 = __funnelshift_l(x1, x1, (r)) ^ x0; }
#define GRP_A RND(13) RND(15) RND(26) RND(6)
#define GRP_B RND(17) RND(29) RND(16) RND(24)
    GRP_A
    x0 += k1;  x1 += ks2 + 1u;
    GRP_B
    x0 += ks2; x1 += k0 + 2u;
    GRP_A
    x0 += k0;  x1 += k1 + 3u;
    GRP_B
    x0 += k1;  x1 += ks2 + 4u;
    GRP_A
    x0 += ks2; x1 += k0 + 5u;
#undef GRP_A
#undef GRP_B
#undef RND
    return x0 ^ x1;
}

// ---------------- top-4 helpers ----------------
__device__ __forceinline__ void ins4(unsigned long long* t, unsigned long long c) {
    if (c > t[0])      { t[3] = t[2]; t[2] = t[1]; t[1] = t[0]; t[0] = c; }
    else if (c > t[1]) { t[3] = t[2]; t[2] = t[1]; t[1] = c; }
    else if (c > t[2]) { t[3] = t[2]; t[2] = c; }
    else if (c > t[3]) { t[3] = c; }
}

__device__ __forceinline__ void warp_merge4(unsigned long long* top) {
    for (int off = 16; off > 0; off >>= 1) {
        unsigned long long o0 = __shfl_xor_sync(0xFFFFFFFFu, top[0], off);
        unsigned long long o1 = __shfl_xor_sync(0xFFFFFFFFu, top[1], off);
        unsigned long long o2 = __shfl_xor_sync(0xFFFFFFFFu, top[2], off);
        unsigned long long o3 = __shfl_xor_sync(0xFFFFFFFFu, top[3], off);
        ins4(top, o0); ins4(top, o1); ins4(top, o2); ins4(top, o3);
    }
}

// ---------------- kernels ----------------
// one warp per row; float4 loads (80 floats = 20 float4). Also zeroes d_out.
__global__ __launch_bounds__(256) void k_labelid(const float* __restrict__ labels,
                                                 float* __restrict__ out,
                                                 int out_size) {
    int warp = (blockIdx.x * blockDim.x + threadIdx.x) >> 5;
    int lane = threadIdx.x & 31;
    if (blockIdx.x == 0 && threadIdx.x < out_size) out[threadIdx.x] = 0.0f;
    if (warp >= BN) return;
    const float4* row = (const float4*)(labels + (size_t)warp * CN);
    unsigned best = 0;
    if (lane < CN / 4) {
        float4 v = row[lane];
        unsigned j = (unsigned)lane * 4u;
        if (v.x > 0.5f) best = j;
        if (v.y > 0.5f) best = j + 1;
        if (v.z > 0.5f) best = j + 2;
        if (v.w > 0.5f) best = j + 3;
    }
    best = __reduce_max_sync(0xFFFFFFFFu, best);
    if (lane == 0) g_lid8[warp] = (unsigned char)best;
}

// PHASE 1 ONLY. grid 4096, block 256; thread t owns j in [16t, 16t+16).
// cand = ((v<<4)+(31-s))*valid = ((v+1)<<4)|(15-s) when valid; 0 invalid.
// Per-thread top-1 stored as u32; no smem, no barriers -> warps retire fast.
__global__ __launch_bounds__(256) void k_select(uint32_t a0, uint32_t a1,
                                                uint32_t b0, uint32_t b1) {
    const int row = blockIdx.x;
    const int tid = threadIdx.x;
    const uint32_t ksA2 = a0 ^ a1 ^ 0x1BD11BDAu;
    const uint32_t ksB2 = b0 ^ b1 ^ 0x1BD11BDAu;

    const uint32_t mylid = (uint32_t)g_lid8[row];
    const uint32_t rep = mylid * 0x01010101u;
    const uint4 l4 = reinterpret_cast<const uint4*>(g_lid8)[tid];
    uint32_t vw[4];
    vw[0] = __vcmpne4(l4.x, rep) & 0x01010101u;
    vw[1] = __vcmpne4(l4.y, rep) & 0x01010101u;
    vw[2] = __vcmpne4(l4.z, rep) & 0x01010101u;
    vw[3] = __vcmpne4(l4.w, rep) & 0x01010101u;

    const uint32_t cbase = (uint32_t)row * (uint32_t)BN + (uint32_t)tid * 16u;

    uint32_t bestA = 0u, bestB = 0u;
    #pragma unroll 4
    for (int s = 0; s < 16; s++) {
        uint32_t bitsA = tf_bits(a0, a1, ksA2, cbase + (uint32_t)s);
        uint32_t bitsB = tf_bits(b0, b1, ksB2, cbase + (uint32_t)s);
        uint32_t v01 = __byte_perm(vw[s >> 2], 0u, 0x4440u | (unsigned)(s & 3));
        uint32_t tA = (bitsA >> 5) & 0xFFFFFFF0u;
        uint32_t tB = (bitsB >> 5) & 0xFFFFFFF0u;
        uint32_t cA = tA * v01 + (uint32_t)(31 - s) * v01;
        uint32_t cB = tB * v01 + (uint32_t)(31 - s) * v01;
        bestA = max(bestA, cA);
        bestB = max(bestB, cB);
    }

    g_best32[0][row][tid] = bestA;
    g_best32[1][row][tid] = bestB;
}

// Barrier-free merge + exact rescan. grid 1024, block 256 = 8 warps;
// warp w handles pair g = blockIdx.x*8+w -> (row = g>>1, dir = g&1).
// Step 1: warp top-4 over the row's 256 per-thread bests.
// Step 2: rescan 4 owner threads x 16 elems = 64 evals, 2 per lane, merge.
__global__ __launch_bounds__(256) void k_merge(uint32_t a0, uint32_t a1,
                                               uint32_t b0, uint32_t b1) {
    const int w = threadIdx.x >> 5;
    const int lane = threadIdx.x & 31;
    const int g = blockIdx.x * 8 + w;
    const int row = g >> 1;
    const int dir = g & 1;

    const uint32_t kk0 = dir ? b0 : a0;
    const uint32_t kk1 = dir ? b1 : a1;
    const uint32_t kks2 = kk0 ^ kk1 ^ 0x1BD11BDAu;
    const uint32_t mylid = (uint32_t)g_lid8[row];

    unsigned long long top[4] = {0ull, 0ull, 0ull, 0ull};
    #pragma unroll
    for (int k = 0; k < 8; k++) {
        int t = lane + 32 * k;
        uint32_t c = g_best32[dir][row][t];
        if (c >= 16u) {
            // val = c>>4 = v+1 ; winning s = 15 - (c&15)
            int j = t * 16 + 15 - (int)(c & 15u);
            unsigned long long p =
                (((unsigned long long)(c >> 4)) << 12) |
                (unsigned long long)(BN - 1 - j);
            ins4(top, p);
        }
    }
    warp_merge4(top);  // all lanes now hold the same top-4 of bests

    // exact rescan: candidate c's owner thread gets all 16 elems re-ranked
    unsigned long long fin[4] = {0ull, 0ull, 0ull, 0ull};
    #pragma unroll
    for (int k = 0; k < 2; k++) {
        int p = lane + 32 * k;          // 0..63
        int c = p >> 4;                 // candidate 0..3
        int s = p & 15;                 // element within owner thread
        unsigned long long tc = top[c];
        if (tc != 0ull) {
            int j0 = BN - 1 - (int)(tc & 0xFFFull);
            int to = j0 >> 4;           // owner thread
            int j = to * 16 + s;
            if ((uint32_t)g_lid8[j] != mylid) {
                uint32_t bits = tf_bits(kk0, kk1, kks2,
                                        (uint32_t)row * (uint32_t)BN + (uint32_t)j);
                unsigned long long pv =
                    (((unsigned long long)((bits >> 9) + 1u)) << 12) |
                    (unsigned long long)(BN - 1 - j);
                ins4(fin, pv);
            }
        }
    }
    warp_merge4(fin);
    if (lane < ERRN)
        g_idx[dir][row][lane] = BN - 1 - (int)(fin[lane] & 0xFFFull);
}

__device__ __forceinline__ float warp_sum(float s) {
    for (int off = 16; off > 0; off >>= 1)
        s += __shfl_xor_sync(0xFFFFFFFFu, s, off);
    return s;
}

__device__ __forceinline__ float dist4(float4 a, float4 b) {
    float dx = a.x - b.x, dy = a.y - b.y, dz = a.z - b.z, dw = a.w - b.w;
    float s = dx * dx + dy * dy + dz * dz + dw * dw;
    s = warp_sum(s);
    return sqrtf(fmaxf(s, 0.0f));
}

// one warp per (row, dir); block 256 = 8 warps = 4 rows; grid 1024.
__global__ __launch_bounds__(256) void k_loss(const float* __restrict__ img,
                                              const float* __restrict__ txt,
                                              float* __restrict__ out) {
    const int w = threadIdx.x >> 5;
    const int lane = threadIdx.x & 31;
    const int i = blockIdx.x * 4 + (w >> 1);
    const int dir = w & 1;

    const float4* img4 = (const float4*)img;
    const float4* txt4 = (const float4*)txt;

    float4 ai = img4[i * 32 + lane];
    float4 ti = txt4[i * 32 + lane];
    float pos = dist4(ai, ti);

    const float4* nsrc = dir ? img4 : txt4;
    float4 anc = dir ? ti : ai;

    float acc = 0.0f;
    #pragma unroll
    for (int k = 0; k < ERRN; k++) {
        int j = g_idx[dir][i][k];
        float4 bj = nsrc[j * 32 + lane];
        float neg = dist4(anc, bj);
        acc += fmaxf(pos - neg + 1.0f, 0.0f);
    }

    __shared__ float ssum[8];
    if (lane == 0) ssum[w] = acc;
    __syncthreads();
    if (threadIdx.x == 0) {
        float t = 0.0f;
        #pragma unroll
        for (int k = 0; k < 8; k++) t += ssum[k];
        atomicAdd(out, t * (1.0f / (float)(BN * ERRN)));
    }
}

// ---------------- launch ----------------
extern "C" void kernel_launch(void* const* d_in, const int* in_sizes, int n_in,
                              void* d_out, int out_size) {
    const float* img    = (const float*)d_in[0];
    const float* txt    = (const float*)d_in[1];
    const float* labels = (const float*)d_in[2];
    float* out = (float*)d_out;

    // jax.random.key(42) -> (0,42); partitionable foldlike split:
    // key_i = threefry((0,42), (0, i)).
    uint32_t a0, a1, b0, b1;
    threefry2x32(0u, 42u, 0u, 0u, a0, a1);  // ks1 (image->text scores)
    threefry2x32(0u, 42u, 0u, 1u, b0, b1);  // ks2 (text->image scores)

    k_labelid<<<512, 256>>>(labels, out, out_size);
    k_select<<<BN, 256>>>(a0, a1, b0, b1);
    k_merge<<<BN / 4, 256>>>(a0, a1, b0, b1);
    k_loss<<<BN / 4, 256>>>(img, txt, out);
}